// round 13
// baseline (speedup 1.0000x reference)
#include <cuda_runtime.h>
#include <cuda_bf16.h>
#include <math.h>
#include <stdint.h>

#define HCH 511
#define LSEQ 2048
#define NM 32
#define CHK 32
#define NCHK 64
#define KPAD 512
#define MPAD 1024
#define TWOH 1022

// ---------------- scratch (device globals) ----------------
__device__ float2 g_w [HCH * NM];
__device__ float2 g_wC[HCH * NM];               // w^CHK (double-computed)
__device__ float  g_KK[HCH * CHK];              // per-channel real taps (mode-summed)
__device__ float2 g_M [HCH * NM * CHK];         // [h][n][k]: c2 * w^{k+1}
__device__ float  g_Y2p[2][TWOH * LSEQ];        // split-K partial GEMM outputs
__device__ float  g_Za[HCH * LSEQ];             // ping-pong activations
__device__ float  g_Zb[HCH * LSEQ];
__device__ __nv_bfloat16 g_Ahi[MPAD * KPAD];    // weight split, [m][k], zero padded
__device__ __nv_bfloat16 g_Alo[MPAD * KPAD];
__device__ __nv_bfloat16 g_Bhi[KPAD * LSEQ];    // activation split, K-major [k][n]
__device__ __nv_bfloat16 g_Blo[KPAD * LSEQ];

__device__ __forceinline__ const float* zsrc_ptr(int sel, const float* ext) {
    return sel < 0 ? ext : (sel == 0 ? g_Za : g_Zb);
}
__device__ __forceinline__ float tanh_fast(float x) {
    float t;
    asm("tanh.approx.f32 %0, %1;" : "=f"(t) : "f"(x));
    return t;
}

// ---------------- prep: discretize + build KK taps and M table ------------------
__global__ __launch_bounds__(32) void kprep_kernel(const float* __restrict__ log_dt,
                                                   const float* __restrict__ Arl,
                                                   const float* __restrict__ Aim,
                                                   const float* __restrict__ Cre,
                                                   const float* __restrict__ Cim) {
    int h    = blockIdx.x;
    int lane = threadIdx.x;
    int idx  = h * NM + lane;
    float dt  = expf(log_dt[h]);
    float Ar  = -expf(Arl[idx]);
    float Ai  = Aim[idx];
    float dar = Ar * dt, dai = Ai * dt;
    float er  = expf(dar);
    float wr  = er * cosf(dai);
    float wi  = er * sinf(dai);
    float e1r = wr - 1.f, e1i = wi;
    float inv = 1.f / (Ar * Ar + Ai * Ai);
    float fr  = (e1r * Ar + e1i * Ai) * inv;
    float fi  = (e1i * Ar - e1r * Ai) * inv;
    float c2r = 2.f * (Cre[idx] * fr - Cim[idx] * fi);
    float c2i = 2.f * (Cre[idx] * fi + Cim[idx] * fr);
    g_w[idx] = make_float2(wr, wi);
    {
        double ph = (double)dai * (double)CHK;
        double sv, cv;
        sincos(ph, &sv, &cv);
        double eC = exp((double)dar * (double)CHK);
        g_wC[idx] = make_float2((float)(eC * cv), (float)(eC * sv));
    }
    float pr = 1.f, pi = 0.f;
    for (int d = 0; d < CHK; d++) {
        float kv = c2r * pr - c2i * pi;
        kv += __shfl_xor_sync(0xffffffffu, kv, 16);
        kv += __shfl_xor_sync(0xffffffffu, kv, 8);
        kv += __shfl_xor_sync(0xffffffffu, kv, 4);
        kv += __shfl_xor_sync(0xffffffffu, kv, 2);
        kv += __shfl_xor_sync(0xffffffffu, kv, 1);
        if (lane == 0) g_KK[h * CHK + d] = kv;
        float npr = fmaf(pr, wr, -pi * wi);
        float npi = fmaf(pr, wi,  pi * wr);
        pr = npr; pi = npi;
        g_M[(h * NM + lane) * CHK + d] =
            make_float2(c2r * pr - c2i * pi, c2r * pi + c2i * pr);
    }
}

// ---------------- prep: split glu_w into bf16 hi/lo; zero pad rows --------------
__global__ void asplit_kernel(const float* __restrict__ gw) {
    int idx = blockIdx.x * blockDim.x + threadIdx.x;   // 0 .. 1024*512-1
    int m = idx >> 9;
    int k = idx & 511;
    float v = (m < TWOH && k < HCH) ? gw[m * HCH + k] : 0.f;
    __nv_bfloat16 hi = __float2bfloat16(v);
    g_Ahi[idx] = hi;
    g_Alo[idx] = __float2bfloat16(v - __bfloat162float(hi));
    if (idx < LSEQ) {   // zero the k=511 pad row of B
        g_Bhi[HCH * LSEQ + idx] = __float2bfloat16(0.f);
        g_Blo[HCH * LSEQ + idx] = __float2bfloat16(0.f);
    }
}

// ---------------- conv: scan for states + table-driven output -------------------
__global__ __launch_bounds__(512) void conv_kernel(const float* __restrict__ Zext,
                                                   const float* __restrict__ Dsk, int src) {
    __shared__ float  zs[LSEQ];
    __shared__ float2 st[NCHK][NM];
    __shared__ float2 sinit[NCHK][NM];
    __shared__ float2 Mts[NM * CHK];     // [n][k]
    __shared__ float  KKs[CHK];
    int h    = blockIdx.x;
    int tid  = threadIdx.x;
    int wid  = tid >> 5;
    int lane = tid & 31;
    const float* zrow = zsrc_ptr(src, Zext) + h * LSEQ;
    for (int i = tid; i < LSEQ; i += 512) zs[i] = zrow[i];
    {
        const float4* Msrc = reinterpret_cast<const float4*>(g_M + h * NM * CHK);
        float4* Mdst = reinterpret_cast<float4*>(Mts);
        Mdst[tid] = Msrc[tid];
    }
    if (tid < CHK) KKs[tid] = g_KK[h * CHK + tid];
    float2 w = g_w[h * NM + lane];
    __syncthreads();

    {   // Pass A: 4 interleaved chunk scans per warp (lane = mode, zero init)
        int b0 = wid * 4 * CHK;
        int b1 = b0 + CHK, b2 = b0 + 2 * CHK, b3 = b0 + 3 * CHK;
        float sr0 = 0.f, si0 = 0.f, sr1 = 0.f, si1 = 0.f;
        float sr2 = 0.f, si2 = 0.f, sr3 = 0.f, si3 = 0.f;
        #pragma unroll 8
        for (int j = 0; j < CHK; j++) {
            float z0 = zs[b0 + j], z1 = zs[b1 + j], z2 = zs[b2 + j], z3 = zs[b3 + j];
            float nr0 = fmaf(w.x, sr0, fmaf(-w.y, si0, z0));
            float ni0 = fmaf(w.y, sr0, w.x * si0);
            float nr1 = fmaf(w.x, sr1, fmaf(-w.y, si1, z1));
            float ni1 = fmaf(w.y, sr1, w.x * si1);
            float nr2 = fmaf(w.x, sr2, fmaf(-w.y, si2, z2));
            float ni2 = fmaf(w.y, sr2, w.x * si2);
            float nr3 = fmaf(w.x, sr3, fmaf(-w.y, si3, z3));
            float ni3 = fmaf(w.y, sr3, w.x * si3);
            sr0 = nr0; si0 = ni0; sr1 = nr1; si1 = ni1;
            sr2 = nr2; si2 = ni2; sr3 = nr3; si3 = ni3;
        }
        st[wid * 4 + 0][lane] = make_float2(sr0, si0);
        st[wid * 4 + 1][lane] = make_float2(sr1, si1);
        st[wid * 4 + 2][lane] = make_float2(sr2, si2);
        st[wid * 4 + 3][lane] = make_float2(sr3, si3);
    }
    __syncthreads();

    if (wid == 0) {   // cross-chunk scan over 64 chunks (lane = mode)
        float2 wc = g_wC[h * NM + lane];
        float cr = 0.f, ci = 0.f;
        #pragma unroll
        for (int jc = 0; jc < NCHK; jc++) {
            sinit[jc][lane] = make_float2(cr, ci);
            float2 b = st[jc][lane];
            float nr = fmaf(wc.x, cr, fmaf(-wc.y, ci, b.x));
            float ni = fmaf(wc.y, cr, fmaf(wc.x, ci, b.y));
            cr = nr; ci = ni;
        }
    }
    __syncthreads();

    // Pass C: lane = timestep k; local taps + state injection per chunk
    float Dh = Dsk[h];
    __nv_bfloat16* bh = g_Bhi + h * LSEQ;
    __nv_bfloat16* bl = g_Blo + h * LSEQ;
    #pragma unroll
    for (int cc = 0; cc < 4; cc++) {
        int c    = wid * 4 + cc;
        int base = c * CHK;
        float y = 0.f;
        #pragma unroll 8
        for (int d = 0; d < CHK; d++) {
            int idx = lane - d;
            float zv = (idx >= 0) ? zs[base + idx] : 0.f;
            y = fmaf(KKs[d], zv, y);
        }
        const float2* s0p = &sinit[c][0];
        #pragma unroll 8
        for (int n = 0; n < NM; n++) {
            float2 m  = Mts[n * CHK + lane];
            float2 s0 = s0p[n];
            y = fmaf(m.x, s0.x, fmaf(-m.y, s0.y, y));
        }
        // epilogue: + D*z, gelu via tanh.approx, bf16 hi/lo split write
        float zv = zs[base + lane];
        float x  = fmaf(Dh, zv, y);
        float u  = 0.7978845608028654f * fmaf(0.044715f, x * x * x, x);
        float t  = tanh_fast(u);
        float hx = 0.5f * x;
        float gl = fmaf(hx, t, hx);
        __nv_bfloat16 hi = __float2bfloat16(gl);
        bh[base + lane] = hi;
        bl[base + lane] = __float2bfloat16(gl - __bfloat162float(hi));
    }
}

// ---------------- HMMA GEMM, split-K x2: z=0 hi*hi (K=512); z=1 hi*lo+lo*hi ------
__device__ __forceinline__ void cp16(uint32_t saddr, const void* gptr) {
    asm volatile("cp.async.ca.shared.global [%0], [%1], 16;" :: "r"(saddr), "l"(gptr));
}
__device__ __forceinline__ uint32_t swzA(int row, int ch) {
    return (uint32_t)(row * 64 + ((ch ^ ((row >> 1) & 3)) << 4));
}
__device__ __forceinline__ uint32_t swzB(int row, int ch) {
    return (uint32_t)(row * 256 + ((ch ^ (row & 7)) << 4));
}

__global__ __launch_bounds__(256, 2) void gemm_hmma_kernel() {
    __shared__ __align__(128) char sA[3][8192];
    __shared__ __align__(128) char sB[3][8192];

    const int t    = threadIdx.x;
    const int wid  = t >> 5;
    const int lane = t & 31;
    const int n0   = blockIdx.x * 128;
    const int m0   = blockIdx.y * 128;
    const int seg  = blockIdx.z;
    const int wm   = (wid & 1) * 64;
    const int wn   = (wid >> 1) * 32;

    const __nv_bfloat16* Aps[2];
    const __nv_bfloat16* Bps[2];
    int niter;
    if (seg == 0) { Aps[0] = g_Ahi; Bps[0] = g_Bhi; Aps[1] = g_Ahi; Bps[1] = g_Bhi; niter = 16; }
    else          { Aps[0] = g_Ahi; Bps[0] = g_Blo; Aps[1] = g_Alo; Bps[1] = g_Bhi; niter = 32; }

    const uint32_t sAu = (uint32_t)__cvta_generic_to_shared(&sA[0][0]);
    const uint32_t sBu = (uint32_t)__cvta_generic_to_shared(&sB[0][0]);

    const int arow0 = t >> 2, ach = t & 3;
    const int arow1 = arow0 + 64;
    const uint32_t aso0 = swzA(arow0, ach);
    const uint32_t aso1 = swzA(arow1, ach);
    const int brow0 = t >> 4,         bch0 = t & 15;
    const int brow1 = (t + 256) >> 4, bch1 = t & 15;
    const uint32_t bso0 = swzB(brow0, bch0);
    const uint32_t bso1 = swzB(brow1, bch1);

    const int ra = lane & 15;
    const int ca = lane >> 4;
    const int bg = lane >> 3;
    const int br = lane & 7;

    float acc[4][4][4];
    #pragma unroll
    for (int i = 0; i < 4; i++)
        #pragma unroll
        for (int j = 0; j < 4; j++)
            #pragma unroll
            for (int q = 0; q < 4; q++) acc[i][j][q] = 0.f;

    #pragma unroll
    for (int st = 0; st < 2; st++) {   // chunks 0,1 are always in sub-seg 0
        const uint32_t dA = sAu + st * 8192;
        const uint32_t dB = sBu + st * 8192;
        cp16(dA + aso0, Aps[0] + (m0 + arow0) * KPAD + st * 32 + ach * 8);
        cp16(dA + aso1, Aps[0] + (m0 + arow1) * KPAD + st * 32 + ach * 8);
        cp16(dB + bso0, Bps[0] + (st * 32 + brow0) * LSEQ + n0 + bch0 * 8);
        cp16(dB + bso1, Bps[0] + (st * 32 + brow1) * LSEQ + n0 + bch1 * 8);
        asm volatile("cp.async.commit_group;" ::: "memory");
    }

    for (int it = 0; it < niter; it++) {
        const int buf = it % 3;
        const uint32_t sAb = sAu + buf * 8192;
        const uint32_t sBb = sBu + buf * 8192;

        asm volatile("cp.async.wait_group 1;" ::: "memory");
        __syncthreads();

        #pragma unroll
        for (int ks = 0; ks < 2; ks++) {
            uint32_t a[4][4], b[4][2];
            #pragma unroll
            for (int mt = 0; mt < 4; mt++) {
                uint32_t ad = sAb + swzA(wm + mt * 16 + ra, ks * 2 + ca);
                asm volatile("ldmatrix.sync.aligned.m8n8.x4.shared.b16 {%0,%1,%2,%3}, [%4];"
                             : "=r"(a[mt][0]), "=r"(a[mt][1]), "=r"(a[mt][2]), "=r"(a[mt][3])
                             : "r"(ad));
            }
            #pragma unroll
            for (int nh = 0; nh < 2; nh++) {
                int krow = ks * 16 + (bg & 1) * 8 + br;
                int nch  = (wn >> 3) + nh * 2 + (bg >> 1);
                uint32_t bd = sBb + swzB(krow, nch);
                uint32_t r0, r1, r2, r3;
                asm volatile("ldmatrix.sync.aligned.m8n8.x4.trans.shared.b16 {%0,%1,%2,%3}, [%4];"
                             : "=r"(r0), "=r"(r1), "=r"(r2), "=r"(r3) : "r"(bd));
                b[nh * 2][0] = r0;     b[nh * 2][1] = r1;
                b[nh * 2 + 1][0] = r2; b[nh * 2 + 1][1] = r3;
            }
            #pragma unroll
            for (int mt = 0; mt < 4; mt++)
                #pragma unroll
                for (int nt = 0; nt < 4; nt++) {
                    asm volatile(
                        "mma.sync.aligned.m16n8k16.row.col.f32.bf16.bf16.f32 "
                        "{%0,%1,%2,%3}, {%4,%5,%6,%7}, {%8,%9}, {%0,%1,%2,%3};"
                        : "+f"(acc[mt][nt][0]), "+f"(acc[mt][nt][1]),
                          "+f"(acc[mt][nt][2]), "+f"(acc[mt][nt][3])
                        : "r"(a[mt][0]), "r"(a[mt][1]), "r"(a[mt][2]), "r"(a[mt][3]),
                          "r"(b[nt][0]), "r"(b[nt][1]));
                }
        }

        if (it + 2 < niter) {
            const int kc  = it + 2;
            const int sub = kc >> 4;
            const int kcm = kc & 15;
            const uint32_t dA = sAu + (kc % 3) * 8192;
            const uint32_t dB = sBu + (kc % 3) * 8192;
            cp16(dA + aso0, Aps[sub] + (m0 + arow0) * KPAD + kcm * 32 + ach * 8);
            cp16(dA + aso1, Aps[sub] + (m0 + arow1) * KPAD + kcm * 32 + ach * 8);
            cp16(dB + bso0, Bps[sub] + (kcm * 32 + brow0) * LSEQ + n0 + bch0 * 8);
            cp16(dB + bso1, Bps[sub] + (kcm * 32 + brow1) * LSEQ + n0 + bch1 * 8);
        }
        asm volatile("cp.async.commit_group;" ::: "memory");
    }

    float* outp = g_Y2p[seg];
    #pragma unroll
    for (int mt = 0; mt < 4; mt++) {
        int mr0 = m0 + wm + mt * 16 + (lane >> 2);
        #pragma unroll
        for (int nt = 0; nt < 4; nt++) {
            int nc = n0 + wn + nt * 8 + (lane & 3) * 2;
            if (mr0 < TWOH)
                *reinterpret_cast<float2*>(&outp[mr0 * LSEQ + nc]) =
                    make_float2(acc[mt][nt][0], acc[mt][nt][1]);
            if (mr0 + 8 < TWOH)
                *reinterpret_cast<float2*>(&outp[(mr0 + 8) * LSEQ + nc]) =
                    make_float2(acc[mt][nt][2], acc[mt][nt][3]);
        }
    }
}

// ---------------- GLU + bias + residual + channel LayerNorm (smem-cached) --------
__global__ __launch_bounds__(512) void lnglu_kernel(const float* __restrict__ Zext,
                                                    const float* __restrict__ gb,
                                                    const float* __restrict__ lng,
                                                    const float* __restrict__ lnb,
                                                    float* __restrict__ ext_out,
                                                    int src, int dst) {
    __shared__ float gsm[HCH * 16];
    __shared__ float r1[32][17], r2[32][17];
    __shared__ float mu_s[16], rs_s[16];

    const float* res = zsrc_ptr(src, Zext);
    float* outp = dst < 0 ? ext_out : (dst == 0 ? g_Za : g_Zb);
    const float* P0 = g_Y2p[0];
    const float* P1 = g_Y2p[1];
    int tx = threadIdx.x & 15;
    int hg = threadIdx.x >> 4;
    int l  = blockIdx.x * 16 + tx;

    float s1 = 0.f, s2 = 0.f;
    for (int h = hg; h < HCH; h += 32) {
        int ia = h * LSEQ + l;
        int ib = (h + HCH) * LSEQ + l;
        float a = P0[ia] + P1[ia] + gb[h];
        float b = P0[ib] + P1[ib] + gb[h + HCH];
        float tb = tanh_fast(0.5f * b);
        float ha = 0.5f * a;
        float g  = fmaf(ha, tb, ha) + res[ia];
        gsm[h * 16 + tx] = g;
        s1 += g; s2 = fmaf(g, g, s2);
    }
    r1[hg][tx] = s1; r2[hg][tx] = s2;
    __syncthreads();
    if (threadIdx.x < 16) {
        float a1 = 0.f, a2 = 0.f;
        #pragma unroll
        for (int j = 0; j < 32; j++) { a1 += r1[j][threadIdx.x]; a2 += r2[j][threadIdx.x]; }
        float mu  = a1 * (1.f / (float)HCH);
        float var = a2 * (1.f / (float)HCH) - mu * mu;
        mu_s[threadIdx.x] = mu;
        rs_s[threadIdx.x] = rsqrtf(var + 1e-5f);
    }
    __syncthreads();
    float mu = mu_s[tx], rs = rs_s[tx];
    for (int h = hg; h < HCH; h += 32) {
        float g = gsm[h * 16 + tx];
        outp[h * LSEQ + l] = (g - mu) * rs * lng[h] + lnb[h];
    }
}

// ---------------- launch ----------------
extern "C" void kernel_launch(void* const* d_in, const int* in_sizes, int n_in,
                              void* d_out, int out_size) {
    const float* Z      = (const float*)d_in[0];
    const float* log_dt = (const float*)d_in[1];
    const float* Arl    = (const float*)d_in[2];
    const float* Aim    = (const float*)d_in[3];
    const float* Cre    = (const float*)d_in[4];
    const float* Cim    = (const float*)d_in[5];
    const float* Dsk    = (const float*)d_in[6];
    const float* gw     = (const float*)d_in[7];
    const float* gb     = (const float*)d_in[8];
    const float* lng    = (const float*)d_in[9];
    const float* lnb    = (const float*)d_in[10];
    float* out = (float*)d_out;

    kprep_kernel<<<HCH, 32>>>(log_dt, Arl, Aim, Cre, Cim);
    asplit_kernel<<<(MPAD * KPAD) / 256, 256>>>(gw);

    const int srcs[4] = {-1, 0, 1, 0};
    const int dsts[4] = { 0, 1, 0, -1};
    for (int layer = 0; layer < 4; ++layer) {
        conv_kernel<<<HCH, 512>>>(Z, Dsk, srcs[layer]);
        gemm_hmma_kernel<<<dim3(16, 8, 2), 256>>>();
        lnglu_kernel<<<128, 512>>>(Z, gb, lng, lnb, out, srcs[layer], dsts[layer]);
    }
}

// round 16
// speedup vs baseline: 1.0916x; 1.0916x over previous
#include <cuda_runtime.h>
#include <cuda_bf16.h>
#include <math.h>
#include <stdint.h>

#define HCH 511
#define LSEQ 2048
#define NM 32
#define CHK 32
#define NCHK 64
#define KPAD 512
#define MPAD 1024
#define TWOH 1022

// ---------------- scratch (device globals) ----------------
__device__ float2 g_w [HCH * NM];
__device__ float2 g_wC[HCH * NM];               // w^CHK (double-computed)
__device__ float  g_KK[HCH * CHK];              // per-channel real taps (mode-summed)
__device__ float2 g_M [HCH * NM * CHK];         // [h][n][k]: c2 * w^{k+1}
__device__ float  g_Y2p[2][TWOH * LSEQ];        // split-K partial GEMM outputs
__device__ float  g_Za[HCH * LSEQ];             // ping-pong activations
__device__ float  g_Zb[HCH * LSEQ];
__device__ __nv_bfloat16 g_Ahi[MPAD * KPAD];    // weight split, [m][k], zero padded
__device__ __nv_bfloat16 g_Alo[MPAD * KPAD];
__device__ __nv_bfloat16 g_Bhi[KPAD * LSEQ];    // activation split, K-major [k][n]
__device__ __nv_bfloat16 g_Blo[KPAD * LSEQ];

__device__ __forceinline__ const float* zsrc_ptr(int sel, const float* ext) {
    return sel < 0 ? ext : (sel == 0 ? g_Za : g_Zb);
}
__device__ __forceinline__ float tanh_fast(float x) {
    float t;
    asm("tanh.approx.f32 %0, %1;" : "=f"(t) : "f"(x));
    return t;
}

// ---------------- prep: discretize + build KK taps and M table ------------------
__global__ __launch_bounds__(32) void kprep_kernel(const float* __restrict__ log_dt,
                                                   const float* __restrict__ Arl,
                                                   const float* __restrict__ Aim,
                                                   const float* __restrict__ Cre,
                                                   const float* __restrict__ Cim) {
    int h    = blockIdx.x;
    int lane = threadIdx.x;
    int idx  = h * NM + lane;
    float dt  = expf(log_dt[h]);
    float Ar  = -expf(Arl[idx]);
    float Ai  = Aim[idx];
    float dar = Ar * dt, dai = Ai * dt;
    float er  = expf(dar);
    float wr  = er * cosf(dai);
    float wi  = er * sinf(dai);
    float e1r = wr - 1.f, e1i = wi;
    float inv = 1.f / (Ar * Ar + Ai * Ai);
    float fr  = (e1r * Ar + e1i * Ai) * inv;
    float fi  = (e1i * Ar - e1r * Ai) * inv;
    float c2r = 2.f * (Cre[idx] * fr - Cim[idx] * fi);
    float c2i = 2.f * (Cre[idx] * fi + Cim[idx] * fr);
    g_w[idx] = make_float2(wr, wi);
    {
        double ph = (double)dai * (double)CHK;
        double sv, cv;
        sincos(ph, &sv, &cv);
        double eC = exp((double)dar * (double)CHK);
        g_wC[idx] = make_float2((float)(eC * cv), (float)(eC * sv));
    }
    float pr = 1.f, pi = 0.f;
    for (int d = 0; d < CHK; d++) {
        float kv = c2r * pr - c2i * pi;
        kv += __shfl_xor_sync(0xffffffffu, kv, 16);
        kv += __shfl_xor_sync(0xffffffffu, kv, 8);
        kv += __shfl_xor_sync(0xffffffffu, kv, 4);
        kv += __shfl_xor_sync(0xffffffffu, kv, 2);
        kv += __shfl_xor_sync(0xffffffffu, kv, 1);
        if (lane == 0) g_KK[h * CHK + d] = kv;
        float npr = fmaf(pr, wr, -pi * wi);
        float npi = fmaf(pr, wi,  pi * wr);
        pr = npr; pi = npi;
        g_M[(h * NM + lane) * CHK + d] =
            make_float2(c2r * pr - c2i * pi, c2r * pi + c2i * pr);
    }
}

// ---------------- prep: split glu_w into bf16 hi/lo; zero pad rows --------------
__global__ void asplit_kernel(const float* __restrict__ gw) {
    int idx = blockIdx.x * blockDim.x + threadIdx.x;   // 0 .. 1024*512-1
    int m = idx >> 9;
    int k = idx & 511;
    float v = (m < TWOH && k < HCH) ? gw[m * HCH + k] : 0.f;
    __nv_bfloat16 hi = __float2bfloat16(v);
    g_Ahi[idx] = hi;
    g_Alo[idx] = __float2bfloat16(v - __bfloat162float(hi));
    if (idx < LSEQ) {   // zero the k=511 pad row of B
        g_Bhi[HCH * LSEQ + idx] = __float2bfloat16(0.f);
        g_Blo[HCH * LSEQ + idx] = __float2bfloat16(0.f);
    }
}

// ---------------- conv: scan for states + table-driven output -------------------
__global__ __launch_bounds__(512) void conv_kernel(const float* __restrict__ Zext,
                                                   const float* __restrict__ Dsk, int src) {
    __shared__ float  zs[LSEQ];
    __shared__ float2 st[NCHK][NM];
    __shared__ float2 sinit[NCHK][NM];
    __shared__ float2 Mts[NM * CHK];     // [n][k]
    __shared__ float  KKs[CHK];
    int h    = blockIdx.x;
    int tid  = threadIdx.x;
    int wid  = tid >> 5;
    int lane = tid & 31;
    const float* zrow = zsrc_ptr(src, Zext) + h * LSEQ;
    for (int i = tid; i < LSEQ; i += 512) zs[i] = zrow[i];
    {
        const float4* Msrc = reinterpret_cast<const float4*>(g_M + h * NM * CHK);
        float4* Mdst = reinterpret_cast<float4*>(Mts);
        Mdst[tid] = Msrc[tid];
    }
    if (tid < CHK) KKs[tid] = g_KK[h * CHK + tid];
    float2 w = g_w[h * NM + lane];
    __syncthreads();

    {   // Pass A: 4 interleaved chunk scans per warp (lane = mode, zero init)
        int b0 = wid * 4 * CHK;
        int b1 = b0 + CHK, b2 = b0 + 2 * CHK, b3 = b0 + 3 * CHK;
        float sr0 = 0.f, si0 = 0.f, sr1 = 0.f, si1 = 0.f;
        float sr2 = 0.f, si2 = 0.f, sr3 = 0.f, si3 = 0.f;
        #pragma unroll 8
        for (int j = 0; j < CHK; j++) {
            float z0 = zs[b0 + j], z1 = zs[b1 + j], z2 = zs[b2 + j], z3 = zs[b3 + j];
            float nr0 = fmaf(w.x, sr0, fmaf(-w.y, si0, z0));
            float ni0 = fmaf(w.y, sr0, w.x * si0);
            float nr1 = fmaf(w.x, sr1, fmaf(-w.y, si1, z1));
            float ni1 = fmaf(w.y, sr1, w.x * si1);
            float nr2 = fmaf(w.x, sr2, fmaf(-w.y, si2, z2));
            float ni2 = fmaf(w.y, sr2, w.x * si2);
            float nr3 = fmaf(w.x, sr3, fmaf(-w.y, si3, z3));
            float ni3 = fmaf(w.y, sr3, w.x * si3);
            sr0 = nr0; si0 = ni0; sr1 = nr1; si1 = ni1;
            sr2 = nr2; si2 = ni2; sr3 = nr3; si3 = ni3;
        }
        st[wid * 4 + 0][lane] = make_float2(sr0, si0);
        st[wid * 4 + 1][lane] = make_float2(sr1, si1);
        st[wid * 4 + 2][lane] = make_float2(sr2, si2);
        st[wid * 4 + 3][lane] = make_float2(sr3, si3);
    }
    __syncthreads();

    if (wid == 0) {   // cross-chunk scan over 64 chunks (lane = mode)
        float2 wc = g_wC[h * NM + lane];
        float cr = 0.f, ci = 0.f;
        #pragma unroll
        for (int jc = 0; jc < NCHK; jc++) {
            sinit[jc][lane] = make_float2(cr, ci);
            float2 b = st[jc][lane];
            float nr = fmaf(wc.x, cr, fmaf(-wc.y, ci, b.x));
            float ni = fmaf(wc.y, cr, fmaf(wc.x, ci, b.y));
            cr = nr; ci = ni;
        }
    }
    __syncthreads();

    // Pass C: lane = timestep k; local taps + state injection per chunk
    float Dh = Dsk[h];
    __nv_bfloat16* bh = g_Bhi + h * LSEQ;
    __nv_bfloat16* bl = g_Blo + h * LSEQ;
    #pragma unroll
    for (int cc = 0; cc < 4; cc++) {
        int c    = wid * 4 + cc;
        int base = c * CHK;
        float y = 0.f;
        #pragma unroll 8
        for (int d = 0; d < CHK; d++) {
            int idx = lane - d;
            float zv = (idx >= 0) ? zs[base + idx] : 0.f;
            y = fmaf(KKs[d], zv, y);
        }
        const float2* s0p = &sinit[c][0];
        #pragma unroll 8
        for (int n = 0; n < NM; n++) {
            float2 m  = Mts[n * CHK + lane];
            float2 s0 = s0p[n];
            y = fmaf(m.x, s0.x, fmaf(-m.y, s0.y, y));
        }
        // epilogue: + D*z, gelu via tanh.approx, bf16 hi/lo split write
        float zv = zs[base + lane];
        float x  = fmaf(Dh, zv, y);
        float u  = 0.7978845608028654f * fmaf(0.044715f, x * x * x, x);
        float t  = tanh_fast(u);
        float hx = 0.5f * x;
        float gl = fmaf(hx, t, hx);
        __nv_bfloat16 hi = __float2bfloat16(gl);
        bh[base + lane] = hi;
        bl[base + lane] = __float2bfloat16(gl - __bfloat162float(hi));
    }
}

// ---------------- HMMA GEMM, balanced split-K x2 over 48 linear chunks -----------
// chunk g in [0,48): segment g>>4 of {(Ahi,Bhi),(Ahi,Blo),(Alo,Bhi)}, offset g&15.
// z=0 -> chunks 0..23; z=1 -> chunks 24..47. Both 24 iters.
__device__ __forceinline__ void cp16(uint32_t saddr, const void* gptr) {
    asm volatile("cp.async.ca.shared.global [%0], [%1], 16;" :: "r"(saddr), "l"(gptr));
}
__device__ __forceinline__ uint32_t swzA(int row, int ch) {
    return (uint32_t)(row * 64 + ((ch ^ ((row >> 1) & 3)) << 4));
}
__device__ __forceinline__ uint32_t swzB(int row, int ch) {
    return (uint32_t)(row * 256 + ((ch ^ (row & 7)) << 4));
}

__global__ __launch_bounds__(256, 2) void gemm_hmma_kernel() {
    __shared__ __align__(128) char sA[3][8192];
    __shared__ __align__(128) char sB[3][8192];

    const int t    = threadIdx.x;
    const int wid  = t >> 5;
    const int lane = t & 31;
    const int n0   = blockIdx.x * 128;
    const int m0   = blockIdx.y * 128;
    const int seg  = blockIdx.z;
    const int wm   = (wid & 1) * 64;
    const int wn   = (wid >> 1) * 32;

    const __nv_bfloat16* Asegs[3] = {g_Ahi, g_Ahi, g_Alo};
    const __nv_bfloat16* Bsegs[3] = {g_Bhi, g_Blo, g_Bhi};
    const int start = seg * 24;
    const int niter = 24;

    const uint32_t sAu = (uint32_t)__cvta_generic_to_shared(&sA[0][0]);
    const uint32_t sBu = (uint32_t)__cvta_generic_to_shared(&sB[0][0]);

    const int arow0 = t >> 2, ach = t & 3;
    const int arow1 = arow0 + 64;
    const uint32_t aso0 = swzA(arow0, ach);
    const uint32_t aso1 = swzA(arow1, ach);
    const int brow0 = t >> 4,         bch0 = t & 15;
    const int brow1 = (t + 256) >> 4, bch1 = t & 15;
    const uint32_t bso0 = swzB(brow0, bch0);
    const uint32_t bso1 = swzB(brow1, bch1);

    const int ra = lane & 15;
    const int ca = lane >> 4;
    const int bg = lane >> 3;
    const int br = lane & 7;

    float acc[4][4][4];
    #pragma unroll
    for (int i = 0; i < 4; i++)
        #pragma unroll
        for (int j = 0; j < 4; j++)
            #pragma unroll
            for (int q = 0; q < 4; q++) acc[i][j][q] = 0.f;

    #pragma unroll
    for (int st = 0; st < 2; st++) {   // prologue: chunks start, start+1
        const int g   = start + st;
        const int sub = g >> 4, kcm = g & 15;
        const __nv_bfloat16* Ap = Asegs[sub];
        const __nv_bfloat16* Bp = Bsegs[sub];
        const uint32_t dA = sAu + st * 8192;
        const uint32_t dB = sBu + st * 8192;
        cp16(dA + aso0, Ap + (m0 + arow0) * KPAD + kcm * 32 + ach * 8);
        cp16(dA + aso1, Ap + (m0 + arow1) * KPAD + kcm * 32 + ach * 8);
        cp16(dB + bso0, Bp + (kcm * 32 + brow0) * LSEQ + n0 + bch0 * 8);
        cp16(dB + bso1, Bp + (kcm * 32 + brow1) * LSEQ + n0 + bch1 * 8);
        asm volatile("cp.async.commit_group;" ::: "memory");
    }

    for (int it = 0; it < niter; it++) {
        const int buf = it % 3;
        const uint32_t sAb = sAu + buf * 8192;
        const uint32_t sBb = sBu + buf * 8192;

        asm volatile("cp.async.wait_group 1;" ::: "memory");
        __syncthreads();

        #pragma unroll
        for (int ks = 0; ks < 2; ks++) {
            uint32_t a[4][4], b[4][2];
            #pragma unroll
            for (int mt = 0; mt < 4; mt++) {
                uint32_t ad = sAb + swzA(wm + mt * 16 + ra, ks * 2 + ca);
                asm volatile("ldmatrix.sync.aligned.m8n8.x4.shared.b16 {%0,%1,%2,%3}, [%4];"
                             : "=r"(a[mt][0]), "=r"(a[mt][1]), "=r"(a[mt][2]), "=r"(a[mt][3])
                             : "r"(ad));
            }
            #pragma unroll
            for (int nh = 0; nh < 2; nh++) {
                int krow = ks * 16 + (bg & 1) * 8 + br;
                int nch  = (wn >> 3) + nh * 2 + (bg >> 1);
                uint32_t bd = sBb + swzB(krow, nch);
                uint32_t r0, r1, r2, r3;
                asm volatile("ldmatrix.sync.aligned.m8n8.x4.trans.shared.b16 {%0,%1,%2,%3}, [%4];"
                             : "=r"(r0), "=r"(r1), "=r"(r2), "=r"(r3) : "r"(bd));
                b[nh * 2][0] = r0;     b[nh * 2][1] = r1;
                b[nh * 2 + 1][0] = r2; b[nh * 2 + 1][1] = r3;
            }
            #pragma unroll
            for (int mt = 0; mt < 4; mt++)
                #pragma unroll
                for (int nt = 0; nt < 4; nt++) {
                    asm volatile(
                        "mma.sync.aligned.m16n8k16.row.col.f32.bf16.bf16.f32 "
                        "{%0,%1,%2,%3}, {%4,%5,%6,%7}, {%8,%9}, {%0,%1,%2,%3};"
                        : "+f"(acc[mt][nt][0]), "+f"(acc[mt][nt][1]),
                          "+f"(acc[mt][nt][2]), "+f"(acc[mt][nt][3])
                        : "r"(a[mt][0]), "r"(a[mt][1]), "r"(a[mt][2]), "r"(a[mt][3]),
                          "r"(b[nt][0]), "r"(b[nt][1]));
                }
        }

        if (it + 2 < niter) {
            const int g   = start + it + 2;
            const int sub = g >> 4, kcm = g & 15;
            const __nv_bfloat16* Ap = Asegs[sub];
            const __nv_bfloat16* Bp = Bsegs[sub];
            const uint32_t dA = sAu + ((it + 2) % 3) * 8192;
            const uint32_t dB = sBu + ((it + 2) % 3) * 8192;
            cp16(dA + aso0, Ap + (m0 + arow0) * KPAD + kcm * 32 + ach * 8);
            cp16(dA + aso1, Ap + (m0 + arow1) * KPAD + kcm * 32 + ach * 8);
            cp16(dB + bso0, Bp + (kcm * 32 + brow0) * LSEQ + n0 + bch0 * 8);
            cp16(dB + bso1, Bp + (kcm * 32 + brow1) * LSEQ + n0 + bch1 * 8);
        }
        asm volatile("cp.async.commit_group;" ::: "memory");
    }

    float* outp = g_Y2p[seg];
    #pragma unroll
    for (int mt = 0; mt < 4; mt++) {
        int mr0 = m0 + wm + mt * 16 + (lane >> 2);
        #pragma unroll
        for (int nt = 0; nt < 4; nt++) {
            int nc = n0 + wn + nt * 8 + (lane & 3) * 2;
            if (mr0 < TWOH)
                *reinterpret_cast<float2*>(&outp[mr0 * LSEQ + nc]) =
                    make_float2(acc[mt][nt][0], acc[mt][nt][1]);
            if (mr0 + 8 < TWOH)
                *reinterpret_cast<float2*>(&outp[(mr0 + 8) * LSEQ + nc]) =
                    make_float2(acc[mt][nt][2], acc[mt][nt][3]);
        }
    }
}

// ---------------- GLU + bias + residual + channel LayerNorm (smem-cached) --------
__global__ __launch_bounds__(512) void lnglu_kernel(const float* __restrict__ Zext,
                                                    const float* __restrict__ gb,
                                                    const float* __restrict__ lng,
                                                    const float* __restrict__ lnb,
                                                    float* __restrict__ ext_out,
                                                    int src, int dst) {
    __shared__ float gsm[HCH * 16];
    __shared__ float r1[32][17], r2[32][17];
    __shared__ float mu_s[16], rs_s[16];

    const float* res = zsrc_ptr(src, Zext);
    float* outp = dst < 0 ? ext_out : (dst == 0 ? g_Za : g_Zb);
    const float* P0 = g_Y2p[0];
    const float* P1 = g_Y2p[1];
    int tx = threadIdx.x & 15;
    int hg = threadIdx.x >> 4;
    int l  = blockIdx.x * 16 + tx;

    float s1 = 0.f, s2 = 0.f;
    for (int h = hg; h < HCH; h += 32) {
        int ia = h * LSEQ + l;
        int ib = (h + HCH) * LSEQ + l;
        float a = P0[ia] + P1[ia] + gb[h];
        float b = P0[ib] + P1[ib] + gb[h + HCH];
        float tb = tanh_fast(0.5f * b);
        float ha = 0.5f * a;
        float g  = fmaf(ha, tb, ha) + res[ia];
        gsm[h * 16 + tx] = g;
        s1 += g; s2 = fmaf(g, g, s2);
    }
    r1[hg][tx] = s1; r2[hg][tx] = s2;
    __syncthreads();
    if (threadIdx.x < 16) {
        float a1 = 0.f, a2 = 0.f;
        #pragma unroll
        for (int j = 0; j < 32; j++) { a1 += r1[j][threadIdx.x]; a2 += r2[j][threadIdx.x]; }
        float mu  = a1 * (1.f / (float)HCH);
        float var = a2 * (1.f / (float)HCH) - mu * mu;
        mu_s[threadIdx.x] = mu;
        rs_s[threadIdx.x] = rsqrtf(var + 1e-5f);
    }
    __syncthreads();
    float mu = mu_s[tx], rs = rs_s[tx];
    for (int h = hg; h < HCH; h += 32) {
        float g = gsm[h * 16 + tx];
        outp[h * LSEQ + l] = (g - mu) * rs * lng[h] + lnb[h];
    }
}

// ---------------- launch ----------------
extern "C" void kernel_launch(void* const* d_in, const int* in_sizes, int n_in,
                              void* d_out, int out_size) {
    const float* Z      = (const float*)d_in[0];
    const float* log_dt = (const float*)d_in[1];
    const float* Arl    = (const float*)d_in[2];
    const float* Aim    = (const float*)d_in[3];
    const float* Cre    = (const float*)d_in[4];
    const float* Cim    = (const float*)d_in[5];
    const float* Dsk    = (const float*)d_in[6];
    const float* gw     = (const float*)d_in[7];
    const float* gb     = (const float*)d_in[8];
    const float* lng    = (const float*)d_in[9];
    const float* lnb    = (const float*)d_in[10];
    float* out = (float*)d_out;

    kprep_kernel<<<HCH, 32>>>(log_dt, Arl, Aim, Cre, Cim);
    asplit_kernel<<<(MPAD * KPAD) / 256, 256>>>(gw);

    const int srcs[4] = {-1, 0, 1, 0};
    const int dsts[4] = { 0, 1, 0, -1};
    for (int layer = 0; layer < 4; ++layer) {
        conv_kernel<<<HCH, 512>>>(Z, Dsk, srcs[layer]);
        gemm_hmma_kernel<<<dim3(16, 8, 2), 256>>>();
        lnglu_kernel<<<128, 512>>>(Z, gb, lng, lnb, out, srcs[layer], dsts[layer]);
    }
}

// round 17
// speedup vs baseline: 1.1016x; 1.0091x over previous
#include <cuda_runtime.h>
#include <cuda_bf16.h>
#include <math.h>
#include <stdint.h>

#define HCH 511
#define LSEQ 2048
#define NM 32
#define CHK 32
#define NCHK 64
#define KPAD 512
#define MPAD 1024
#define TWOH 1022

// ---------------- scratch (device globals) ----------------
__device__ float2 g_w [HCH * NM];
__device__ float2 g_wC[HCH * NM];               // w^CHK (double-computed)
__device__ float  g_KK[HCH * CHK];              // per-channel real taps (mode-summed)
__device__ float2 g_M [HCH * NM * CHK];         // [h][n][k]: c2 * w^{k+1}
__device__ float  g_Y2p[3][TWOH * LSEQ];        // split-K partial GEMM outputs
__device__ float  g_Za[HCH * LSEQ];             // ping-pong activations
__device__ float  g_Zb[HCH * LSEQ];
__device__ __nv_bfloat16 g_Ahi[MPAD * KPAD];    // weight split, [m][k], zero padded
__device__ __nv_bfloat16 g_Alo[MPAD * KPAD];
__device__ __nv_bfloat16 g_Bhi[KPAD * LSEQ];    // activation split, K-major [k][n]
__device__ __nv_bfloat16 g_Blo[KPAD * LSEQ];

__device__ __forceinline__ const float* zsrc_ptr(int sel, const float* ext) {
    return sel < 0 ? ext : (sel == 0 ? g_Za : g_Zb);
}
__device__ __forceinline__ float tanh_fast(float x) {
    float t;
    asm("tanh.approx.f32 %0, %1;" : "=f"(t) : "f"(x));
    return t;
}

// ---------------- prep: discretize + build KK taps and M table ------------------
__global__ __launch_bounds__(32) void kprep_kernel(const float* __restrict__ log_dt,
                                                   const float* __restrict__ Arl,
                                                   const float* __restrict__ Aim,
                                                   const float* __restrict__ Cre,
                                                   const float* __restrict__ Cim) {
    int h    = blockIdx.x;
    int lane = threadIdx.x;
    int idx  = h * NM + lane;
    float dt  = expf(log_dt[h]);
    float Ar  = -expf(Arl[idx]);
    float Ai  = Aim[idx];
    float dar = Ar * dt, dai = Ai * dt;
    float er  = expf(dar);
    float wr  = er * cosf(dai);
    float wi  = er * sinf(dai);
    float e1r = wr - 1.f, e1i = wi;
    float inv = 1.f / (Ar * Ar + Ai * Ai);
    float fr  = (e1r * Ar + e1i * Ai) * inv;
    float fi  = (e1i * Ar - e1r * Ai) * inv;
    float c2r = 2.f * (Cre[idx] * fr - Cim[idx] * fi);
    float c2i = 2.f * (Cre[idx] * fi + Cim[idx] * fr);
    g_w[idx] = make_float2(wr, wi);
    {
        double ph = (double)dai * (double)CHK;
        double sv, cv;
        sincos(ph, &sv, &cv);
        double eC = exp((double)dar * (double)CHK);
        g_wC[idx] = make_float2((float)(eC * cv), (float)(eC * sv));
    }
    float pr = 1.f, pi = 0.f;
    for (int d = 0; d < CHK; d++) {
        float kv = c2r * pr - c2i * pi;
        kv += __shfl_xor_sync(0xffffffffu, kv, 16);
        kv += __shfl_xor_sync(0xffffffffu, kv, 8);
        kv += __shfl_xor_sync(0xffffffffu, kv, 4);
        kv += __shfl_xor_sync(0xffffffffu, kv, 2);
        kv += __shfl_xor_sync(0xffffffffu, kv, 1);
        if (lane == 0) g_KK[h * CHK + d] = kv;
        float npr = fmaf(pr, wr, -pi * wi);
        float npi = fmaf(pr, wi,  pi * wr);
        pr = npr; pi = npi;
        g_M[(h * NM + lane) * CHK + d] =
            make_float2(c2r * pr - c2i * pi, c2r * pi + c2i * pr);
    }
}

// ---------------- prep: split glu_w into bf16 hi/lo; zero pad rows --------------
__global__ void asplit_kernel(const float* __restrict__ gw) {
    int idx = blockIdx.x * blockDim.x + threadIdx.x;   // 0 .. 1024*512-1
    int m = idx >> 9;
    int k = idx & 511;
    float v = (m < TWOH && k < HCH) ? gw[m * HCH + k] : 0.f;
    __nv_bfloat16 hi = __float2bfloat16(v);
    g_Ahi[idx] = hi;
    g_Alo[idx] = __float2bfloat16(v - __bfloat162float(hi));
    if (idx < LSEQ) {   // zero the k=511 pad row of B
        g_Bhi[HCH * LSEQ + idx] = __float2bfloat16(0.f);
        g_Blo[HCH * LSEQ + idx] = __float2bfloat16(0.f);
    }
}

// ---------------- conv: scan for states + table-driven output -------------------
__global__ __launch_bounds__(512) void conv_kernel(const float* __restrict__ Zext,
                                                   const float* __restrict__ Dsk, int src) {
    __shared__ float  zs[LSEQ];
    __shared__ float2 st[NCHK][NM];
    __shared__ float2 sinit[NCHK][NM];
    __shared__ float2 Mts[NM * CHK];     // [n][k]
    __shared__ float  KKs[CHK];
    int h    = blockIdx.x;
    int tid  = threadIdx.x;
    int wid  = tid >> 5;
    int lane = tid & 31;
    const float* zrow = zsrc_ptr(src, Zext) + h * LSEQ;
    for (int i = tid; i < LSEQ; i += 512) zs[i] = zrow[i];
    {
        const float4* Msrc = reinterpret_cast<const float4*>(g_M + h * NM * CHK);
        float4* Mdst = reinterpret_cast<float4*>(Mts);
        Mdst[tid] = Msrc[tid];
    }
    if (tid < CHK) KKs[tid] = g_KK[h * CHK + tid];
    float2 w = g_w[h * NM + lane];
    __syncthreads();

    {   // Pass A: 4 interleaved chunk scans per warp (lane = mode, zero init)
        int b0 = wid * 4 * CHK;
        int b1 = b0 + CHK, b2 = b0 + 2 * CHK, b3 = b0 + 3 * CHK;
        float sr0 = 0.f, si0 = 0.f, sr1 = 0.f, si1 = 0.f;
        float sr2 = 0.f, si2 = 0.f, sr3 = 0.f, si3 = 0.f;
        #pragma unroll 8
        for (int j = 0; j < CHK; j++) {
            float z0 = zs[b0 + j], z1 = zs[b1 + j], z2 = zs[b2 + j], z3 = zs[b3 + j];
            float nr0 = fmaf(w.x, sr0, fmaf(-w.y, si0, z0));
            float ni0 = fmaf(w.y, sr0, w.x * si0);
            float nr1 = fmaf(w.x, sr1, fmaf(-w.y, si1, z1));
            float ni1 = fmaf(w.y, sr1, w.x * si1);
            float nr2 = fmaf(w.x, sr2, fmaf(-w.y, si2, z2));
            float ni2 = fmaf(w.y, sr2, w.x * si2);
            float nr3 = fmaf(w.x, sr3, fmaf(-w.y, si3, z3));
            float ni3 = fmaf(w.y, sr3, w.x * si3);
            sr0 = nr0; si0 = ni0; sr1 = nr1; si1 = ni1;
            sr2 = nr2; si2 = ni2; sr3 = nr3; si3 = ni3;
        }
        st[wid * 4 + 0][lane] = make_float2(sr0, si0);
        st[wid * 4 + 1][lane] = make_float2(sr1, si1);
        st[wid * 4 + 2][lane] = make_float2(sr2, si2);
        st[wid * 4 + 3][lane] = make_float2(sr3, si3);
    }
    __syncthreads();

    if (wid == 0) {   // cross-chunk scan over 64 chunks (lane = mode)
        float2 wc = g_wC[h * NM + lane];
        float cr = 0.f, ci = 0.f;
        #pragma unroll
        for (int jc = 0; jc < NCHK; jc++) {
            sinit[jc][lane] = make_float2(cr, ci);
            float2 b = st[jc][lane];
            float nr = fmaf(wc.x, cr, fmaf(-wc.y, ci, b.x));
            float ni = fmaf(wc.y, cr, fmaf(wc.x, ci, b.y));
            cr = nr; ci = ni;
        }
    }
    __syncthreads();

    // Pass C: lane = timestep k; local taps + state injection per chunk
    float Dh = Dsk[h];
    __nv_bfloat16* bh = g_Bhi + h * LSEQ;
    __nv_bfloat16* bl = g_Blo + h * LSEQ;
    #pragma unroll
    for (int cc = 0; cc < 4; cc++) {
        int c    = wid * 4 + cc;
        int base = c * CHK;
        float y = 0.f;
        #pragma unroll 8
        for (int d = 0; d < CHK; d++) {
            int idx = lane - d;
            float zv = (idx >= 0) ? zs[base + idx] : 0.f;
            y = fmaf(KKs[d], zv, y);
        }
        const float2* s0p = &sinit[c][0];
        #pragma unroll 8
        for (int n = 0; n < NM; n++) {
            float2 m  = Mts[n * CHK + lane];
            float2 s0 = s0p[n];
            y = fmaf(m.x, s0.x, fmaf(-m.y, s0.y, y));
        }
        // epilogue: + D*z, gelu via tanh.approx, bf16 hi/lo split write
        float zv = zs[base + lane];
        float x  = fmaf(Dh, zv, y);
        float u  = 0.7978845608028654f * fmaf(0.044715f, x * x * x, x);
        float t  = tanh_fast(u);
        float hx = 0.5f * x;
        float gl = fmaf(hx, t, hx);
        __nv_bfloat16 hi = __float2bfloat16(gl);
        bh[base + lane] = hi;
        bl[base + lane] = __float2bfloat16(gl - __bfloat162float(hi));
    }
}

// ---------------- HMMA GEMM, split-K x3 (measured-best config) -------------------
__device__ __forceinline__ void cp16(uint32_t saddr, const void* gptr) {
    asm volatile("cp.async.ca.shared.global [%0], [%1], 16;" :: "r"(saddr), "l"(gptr));
}
__device__ __forceinline__ uint32_t swzA(int row, int ch) {
    return (uint32_t)(row * 64 + ((ch ^ ((row >> 1) & 3)) << 4));
}
__device__ __forceinline__ uint32_t swzB(int row, int ch) {
    return (uint32_t)(row * 256 + ((ch ^ (row & 7)) << 4));
}

__global__ __launch_bounds__(256, 2) void gemm_hmma_kernel() {
    __shared__ __align__(128) char sA[3][8192];
    __shared__ __align__(128) char sB[3][8192];

    const int t    = threadIdx.x;
    const int wid  = t >> 5;
    const int lane = t & 31;
    const int n0   = blockIdx.x * 128;
    const int m0   = blockIdx.y * 128;
    const int seg  = blockIdx.z;
    const int wm   = (wid & 1) * 64;
    const int wn   = (wid >> 1) * 32;

    const __nv_bfloat16* Ap = (seg == 2) ? g_Alo : g_Ahi;
    const __nv_bfloat16* Bp = (seg == 1) ? g_Blo : g_Bhi;

    const uint32_t sAu = (uint32_t)__cvta_generic_to_shared(&sA[0][0]);
    const uint32_t sBu = (uint32_t)__cvta_generic_to_shared(&sB[0][0]);

    const int arow0 = t >> 2, ach = t & 3;
    const int arow1 = arow0 + 64;
    const uint32_t aso0 = swzA(arow0, ach);
    const uint32_t aso1 = swzA(arow1, ach);
    const int brow0 = t >> 4,         bch0 = t & 15;
    const int brow1 = (t + 256) >> 4, bch1 = t & 15;
    const uint32_t bso0 = swzB(brow0, bch0);
    const uint32_t bso1 = swzB(brow1, bch1);

    const int ra = lane & 15;
    const int ca = lane >> 4;
    const int bg = lane >> 3;
    const int br = lane & 7;

    float acc[4][4][4];
    #pragma unroll
    for (int i = 0; i < 4; i++)
        #pragma unroll
        for (int j = 0; j < 4; j++)
            #pragma unroll
            for (int q = 0; q < 4; q++) acc[i][j][q] = 0.f;

    #pragma unroll
    for (int st = 0; st < 2; st++) {
        const uint32_t dA = sAu + st * 8192;
        const uint32_t dB = sBu + st * 8192;
        cp16(dA + aso0, Ap + (m0 + arow0) * KPAD + st * 32 + ach * 8);
        cp16(dA + aso1, Ap + (m0 + arow1) * KPAD + st * 32 + ach * 8);
        cp16(dB + bso0, Bp + (st * 32 + brow0) * LSEQ + n0 + bch0 * 8);
        cp16(dB + bso1, Bp + (st * 32 + brow1) * LSEQ + n0 + bch1 * 8);
        asm volatile("cp.async.commit_group;" ::: "memory");
    }

    for (int it = 0; it < 16; it++) {
        const int buf = it % 3;
        const uint32_t sAb = sAu + buf * 8192;
        const uint32_t sBb = sBu + buf * 8192;

        asm volatile("cp.async.wait_group 1;" ::: "memory");
        __syncthreads();

        #pragma unroll
        for (int ks = 0; ks < 2; ks++) {
            uint32_t a[4][4], b[4][2];
            #pragma unroll
            for (int mt = 0; mt < 4; mt++) {
                uint32_t ad = sAb + swzA(wm + mt * 16 + ra, ks * 2 + ca);
                asm volatile("ldmatrix.sync.aligned.m8n8.x4.shared.b16 {%0,%1,%2,%3}, [%4];"
                             : "=r"(a[mt][0]), "=r"(a[mt][1]), "=r"(a[mt][2]), "=r"(a[mt][3])
                             : "r"(ad));
            }
            #pragma unroll
            for (int nh = 0; nh < 2; nh++) {
                int krow = ks * 16 + (bg & 1) * 8 + br;
                int nch  = (wn >> 3) + nh * 2 + (bg >> 1);
                uint32_t bd = sBb + swzB(krow, nch);
                uint32_t r0, r1, r2, r3;
                asm volatile("ldmatrix.sync.aligned.m8n8.x4.trans.shared.b16 {%0,%1,%2,%3}, [%4];"
                             : "=r"(r0), "=r"(r1), "=r"(r2), "=r"(r3) : "r"(bd));
                b[nh * 2][0] = r0;     b[nh * 2][1] = r1;
                b[nh * 2 + 1][0] = r2; b[nh * 2 + 1][1] = r3;
            }
            #pragma unroll
            for (int mt = 0; mt < 4; mt++)
                #pragma unroll
                for (int nt = 0; nt < 4; nt++) {
                    asm volatile(
                        "mma.sync.aligned.m16n8k16.row.col.f32.bf16.bf16.f32 "
                        "{%0,%1,%2,%3}, {%4,%5,%6,%7}, {%8,%9}, {%0,%1,%2,%3};"
                        : "+f"(acc[mt][nt][0]), "+f"(acc[mt][nt][1]),
                          "+f"(acc[mt][nt][2]), "+f"(acc[mt][nt][3])
                        : "r"(a[mt][0]), "r"(a[mt][1]), "r"(a[mt][2]), "r"(a[mt][3]),
                          "r"(b[nt][0]), "r"(b[nt][1]));
                }
        }

        if (it + 2 < 16) {
            const int kc = it + 2;
            const uint32_t dA = sAu + (kc % 3) * 8192;
            const uint32_t dB = sBu + (kc % 3) * 8192;
            cp16(dA + aso0, Ap + (m0 + arow0) * KPAD + kc * 32 + ach * 8);
            cp16(dA + aso1, Ap + (m0 + arow1) * KPAD + kc * 32 + ach * 8);
            cp16(dB + bso0, Bp + (kc * 32 + brow0) * LSEQ + n0 + bch0 * 8);
            cp16(dB + bso1, Bp + (kc * 32 + brow1) * LSEQ + n0 + bch1 * 8);
        }
        asm volatile("cp.async.commit_group;" ::: "memory");
    }

    float* outp = g_Y2p[seg];
    #pragma unroll
    for (int mt = 0; mt < 4; mt++) {
        int mr0 = m0 + wm + mt * 16 + (lane >> 2);
        #pragma unroll
        for (int nt = 0; nt < 4; nt++) {
            int nc = n0 + wn + nt * 8 + (lane & 3) * 2;
            if (mr0 < TWOH)
                *reinterpret_cast<float2*>(&outp[mr0 * LSEQ + nc]) =
                    make_float2(acc[mt][nt][0], acc[mt][nt][1]);
            if (mr0 + 8 < TWOH)
                *reinterpret_cast<float2*>(&outp[(mr0 + 8) * LSEQ + nc]) =
                    make_float2(acc[mt][nt][2], acc[mt][nt][3]);
        }
    }
}

// ---------------- GLU + bias + residual + channel LayerNorm (smem-cached) --------
__global__ __launch_bounds__(512) void lnglu_kernel(const float* __restrict__ Zext,
                                                    const float* __restrict__ gb,
                                                    const float* __restrict__ lng,
                                                    const float* __restrict__ lnb,
                                                    float* __restrict__ ext_out,
                                                    int src, int dst) {
    __shared__ float gsm[HCH * 16];
    __shared__ float r1[32][17], r2[32][17];
    __shared__ float mu_s[16], rs_s[16];

    const float* res = zsrc_ptr(src, Zext);
    float* outp = dst < 0 ? ext_out : (dst == 0 ? g_Za : g_Zb);
    const float* P0 = g_Y2p[0];
    const float* P1 = g_Y2p[1];
    const float* P2 = g_Y2p[2];
    int tx = threadIdx.x & 15;
    int hg = threadIdx.x >> 4;
    int l  = blockIdx.x * 16 + tx;

    float s1 = 0.f, s2 = 0.f;
    for (int h = hg; h < HCH; h += 32) {
        int ia = h * LSEQ + l;
        int ib = (h + HCH) * LSEQ + l;
        float a = (P0[ia] + P1[ia]) + P2[ia] + gb[h];
        float b = (P0[ib] + P1[ib]) + P2[ib] + gb[h + HCH];
        float tb = tanh_fast(0.5f * b);
        float ha = 0.5f * a;
        float g  = fmaf(ha, tb, ha) + res[ia];
        gsm[h * 16 + tx] = g;
        s1 += g; s2 = fmaf(g, g, s2);
    }
    r1[hg][tx] = s1; r2[hg][tx] = s2;
    __syncthreads();
    if (threadIdx.x < 16) {
        float a1 = 0.f, a2 = 0.f;
        #pragma unroll
        for (int j = 0; j < 32; j++) { a1 += r1[j][threadIdx.x]; a2 += r2[j][threadIdx.x]; }
        float mu  = a1 * (1.f / (float)HCH);
        float var = a2 * (1.f / (float)HCH) - mu * mu;
        mu_s[threadIdx.x] = mu;
        rs_s[threadIdx.x] = rsqrtf(var + 1e-5f);
    }
    __syncthreads();
    float mu = mu_s[tx], rs = rs_s[tx];
    for (int h = hg; h < HCH; h += 32) {
        float g = gsm[h * 16 + tx];
        outp[h * LSEQ + l] = (g - mu) * rs * lng[h] + lnb[h];
    }
}

// ---------------- launch ----------------
extern "C" void kernel_launch(void* const* d_in, const int* in_sizes, int n_in,
                              void* d_out, int out_size) {
    const float* Z      = (const float*)d_in[0];
    const float* log_dt = (const float*)d_in[1];
    const float* Arl    = (const float*)d_in[2];
    const float* Aim    = (const float*)d_in[3];
    const float* Cre    = (const float*)d_in[4];
    const float* Cim    = (const float*)d_in[5];
    const float* Dsk    = (const float*)d_in[6];
    const float* gw     = (const float*)d_in[7];
    const float* gb     = (const float*)d_in[8];
    const float* lng    = (const float*)d_in[9];
    const float* lnb    = (const float*)d_in[10];
    float* out = (float*)d_out;

    kprep_kernel<<<HCH, 32>>>(log_dt, Arl, Aim, Cre, Cim);
    asplit_kernel<<<(MPAD * KPAD) / 256, 256>>>(gw);

    const int srcs[4] = {-1, 0, 1, 0};
    const int dsts[4] = { 0, 1, 0, -1};
    for (int layer = 0; layer < 4; ++layer) {
        conv_kernel<<<HCH, 512>>>(Z, Dsk, srcs[layer]);
        gemm_hmma_kernel<<<dim3(16, 8, 3), 256>>>();
        lnglu_kernel<<<128, 512>>>(Z, gb, lng, lnb, out, srcs[layer], dsts[layer]);
    }
}